// round 16
// baseline (speedup 1.0000x reference)
#include <cuda_runtime.h>
#include <cuda_fp16.h>
#include <cstdint>

#define BB 8
#define LL 1024
#define SSd 1024
#define HH 12
#define EE 64
#define DD 64
#define NT 256

#define KSTR 144                    // bytes per f16 row (64 f16 + 16B pad)
#define KTILE (128 * KSTR)          // 18432
#define SM_KW (4 * KTILE)           // working K slot (stages 4-7)
#define SM_V  (5 * KTILE)           // V slot
#define SM_ROW (6 * KTILE)          // rowsums
#define SMEM_TOTAL (SM_ROW + 512)   // 111104 B -> 2 CTAs/SM

// m16n8k16 row.col f32.f16.f16.f32
__device__ __forceinline__ void mma16816(float* c, const uint32_t* a, uint32_t b0, uint32_t b1) {
    asm volatile(
        "mma.sync.aligned.m16n8k16.row.col.f32.f16.f16.f32 "
        "{%0,%1,%2,%3}, {%4,%5,%6,%7}, {%8,%9}, {%0,%1,%2,%3};"
        : "+f"(c[0]), "+f"(c[1]), "+f"(c[2]), "+f"(c[3])
        : "r"(a[0]), "r"(a[1]), "r"(a[2]), "r"(a[3]), "r"(b0), "r"(b1));
}

__device__ __forceinline__ void ldsm4(uint32_t* r, uint32_t saddr) {
    asm volatile("ldmatrix.sync.aligned.m8n8.x4.shared.b16 {%0,%1,%2,%3}, [%4];"
        : "=r"(r[0]), "=r"(r[1]), "=r"(r[2]), "=r"(r[3]) : "r"(saddr));
}
__device__ __forceinline__ void ldsm4t(uint32_t* r, uint32_t saddr) {
    asm volatile("ldmatrix.sync.aligned.m8n8.x4.trans.shared.b16 {%0,%1,%2,%3}, [%4];"
        : "=r"(r[0]), "=r"(r[1]), "=r"(r[2]), "=r"(r[3]) : "r"(saddr));
}

// fast exp2(y), log2-domain input; deg-4 Taylor, no clamp (|y| bounded by data)
__device__ __forceinline__ float fast_exp2(float y) {
    float nf = y + 12582912.0f;
    float f  = y - (nf - 12582912.0f);
    int   ni = __float_as_int(nf) - 0x4B400000;
    float p = 0.009618129107628477f;
    p = fmaf(p, f, 0.05550410866482158f);
    p = fmaf(p, f, 0.2402265069591007f);
    p = fmaf(p, f, 0.6931471805599453f);
    p = fmaf(p, f, 1.0f);
    return __int_as_float((ni + 127) << 23) * p;
}

// 2-term f16 split
__device__ __forceinline__ void split2h(float a, float b, uint32_t& hi, uint32_t& lo) {
    __half ha = __float2half_rn(a), hb = __float2half_rn(b);
    __half2 hh = __halves2half2(ha, hb);
    hi = *reinterpret_cast<uint32_t*>(&hh);
    __half2 ll = __floats2half2_rn(a - __half2float(ha), b - __half2float(hb));
    lo = *reinterpret_cast<uint32_t*>(&ll);
}
__device__ __forceinline__ uint32_t pack2h(float a, float b) {
    __half2 hh = __floats2half2_rn(a, b);
    return *reinterpret_cast<uint32_t*>(&hh);
}

__global__ void __launch_bounds__(NT, 2)
attn_mma(const float* __restrict__ q, const float* __restrict__ k,
         const float* __restrict__ v, const float* __restrict__ scale,
         float* __restrict__ out)
{
    extern __shared__ char smc[];
    float* sRow = reinterpret_cast<float*>(smc + SM_ROW);
    const uint32_t smem_u = (uint32_t)__cvta_generic_to_shared(smc);

    const int tid  = threadIdx.x;
    const int wid  = tid >> 5;
    const int lane = tid & 31;
    const int g    = lane >> 2;
    const int m    = lane & 3;

    const int lt = blockIdx.x & 7;
    const int h  = (blockIdx.x >> 3) % HH;
    const int b  = blockIdx.x / (8 * HH);
    const int row0 = lt * 128;
    const int wrow = wid * 16;

    const float sc = __ldg(scale + h) * 1.4426950408889634f;   // fold log2(e)

    const float* Qp = q + (((size_t)b * LL + row0) * HH + h) * EE;
    const float* Kp = k + ((size_t)b * SSd * HH + h) * EE;
    const float* Vp = v + ((size_t)b * SSd * HH + h) * DD;
    float* Op = out + (((size_t)b * LL + row0) * HH + h) * DD;
    float* Ap = out + (size_t)BB * LL * HH * DD
                    + (((size_t)b * HH + h) * LL + row0) * (size_t)SSd;

    // fp32 -> f16 tile converter: COALESCED round-12 mapping
    // (16 lanes per 256B row, one LDG.128 + one STS.64 per iteration)
    auto conv_tile = [&](const float* src, int dstoff) {
        #pragma unroll
        for (int i = 0; i < 8; ++i) {
            int idx = tid + i * NT;          // 0..2047
            int s = idx >> 4, e4 = idx & 15;
            float4 t = *reinterpret_cast<const float4*>(
                src + (size_t)s * (HH * EE) + e4 * 4);
            *reinterpret_cast<uint2*>(smc + dstoff + s * KSTR + e4 * 8) =
                make_uint2(pack2h(t.x, t.y), pack2h(t.z, t.w));
        }
    };

    // lane-parts of ldsm bases (tile offset added per stage)
    const uint32_t laneQK = smem_u + (lane & 7) * KSTR + ((lane >> 3) & 1) * 16
                          + (lane >> 4) * (8 * KSTR);
    const uint32_t basePV = smem_u + SM_V
                          + ((lane & 7) + ((lane >> 3) & 1) * 8) * KSTR
                          + (lane >> 4) * 16;

    // ---- Q fragments (persistent): 4 k-tiles, f16 hi+lo ----
    uint32_t qh[4][4], ql[4][4];
    {
        const float* q0 = Qp + (size_t)(wrow + g) * (HH * EE);
        const float* q1 = Qp + (size_t)(wrow + g + 8) * (HH * EE);
        #pragma unroll
        for (int kt = 0; kt < 4; ++kt) {
            int e0 = kt * 16 + 2 * m;
            float2 a0 = *reinterpret_cast<const float2*>(q0 + e0);
            float2 a1 = *reinterpret_cast<const float2*>(q1 + e0);
            float2 a2 = *reinterpret_cast<const float2*>(q0 + e0 + 8);
            float2 a3 = *reinterpret_cast<const float2*>(q1 + e0 + 8);
            split2h(a0.x * sc, a0.y * sc, qh[kt][0], ql[kt][0]);
            split2h(a1.x * sc, a1.y * sc, qh[kt][1], ql[kt][1]);
            split2h(a2.x * sc, a2.y * sc, qh[kt][2], ql[kt][2]);
            split2h(a3.x * sc, a3.y * sc, qh[kt][3], ql[kt][3]);
        }
    }

    const int lrow_lo = wrow + g;     // diag col within stage st==lt
    const int lrow_hi = lrow_lo + 8;
    float rsum_lo = 0.f, rsum_hi = 0.f;

    // ======== PASS 1: rowsums (Q-hi only); stages 0-3 convert K into cache slots ========
    for (int st = 0; st < 8; ++st) {
        if (st >= 5) __syncthreads();          // only Kwork overwrites need a pre-sync
        const int koff = (st < 4) ? st * KTILE : SM_KW;
        conv_tile(Kp + (size_t)(st * 128) * (HH * EE), koff);
        __syncthreads();

        const uint32_t bq = laneQK + koff;
        const bool diag = (st == lt);
        #pragma unroll
        for (int pkt = 0; pkt < 8; ++pkt) {
            float s0[4] = {0.f, 0.f, 0.f, 0.f};
            float s1[4] = {0.f, 0.f, 0.f, 0.f};
            #pragma unroll
            for (int kt = 0; kt < 4; ++kt) {
                uint32_t bb[4];
                ldsm4(bb, bq + pkt * (16 * KSTR) + kt * 32);
                mma16816(s0, qh[kt], bb[0], bb[1]);
                mma16816(s1, qh[kt], bb[2], bb[3]);
            }
            s0[0] = fast_exp2(s0[0]); s0[1] = fast_exp2(s0[1]);
            s0[2] = fast_exp2(s0[2]); s0[3] = fast_exp2(s0[3]);
            s1[0] = fast_exp2(s1[0]); s1[1] = fast_exp2(s1[1]);
            s1[2] = fast_exp2(s1[2]); s1[3] = fast_exp2(s1[3]);
            if (diag) {
                int c0 = pkt * 16 + 2 * m;
                int c1 = c0 + 8;
                if (c0 == lrow_lo)     s0[0] = 0.f;
                if (c0 + 1 == lrow_lo) s0[1] = 0.f;
                if (c0 == lrow_hi)     s0[2] = 0.f;
                if (c0 + 1 == lrow_hi) s0[3] = 0.f;
                if (c1 == lrow_lo)     s1[0] = 0.f;
                if (c1 + 1 == lrow_lo) s1[1] = 0.f;
                if (c1 == lrow_hi)     s1[2] = 0.f;
                if (c1 + 1 == lrow_hi) s1[3] = 0.f;
            }
            rsum_lo += (s0[0] + s0[1]) + (s1[0] + s1[1]);
            rsum_hi += (s0[2] + s0[3]) + (s1[2] + s1[3]);
        }
    }

    rsum_lo += __shfl_xor_sync(0xffffffffu, rsum_lo, 1);
    rsum_lo += __shfl_xor_sync(0xffffffffu, rsum_lo, 2);
    rsum_hi += __shfl_xor_sync(0xffffffffu, rsum_hi, 1);
    rsum_hi += __shfl_xor_sync(0xffffffffu, rsum_hi, 2);
    if (m == 0) {
        sRow[wrow + g] = rsum_lo;
        sRow[wrow + g + 8] = rsum_hi;
    }
    __syncthreads();
    const float ri_lo = 1.0f / sRow[wrow + g];
    const float ri_hi = 1.0f / sRow[wrow + g + 8];

    float o[8][4];
    #pragma unroll
    for (int i = 0; i < 8; ++i)
        #pragma unroll
        for (int j = 0; j < 4; ++j) o[i][j] = 0.f;

    float* Arow_lo = Ap + (size_t)(wrow + g) * SSd;
    float* Arow_hi = Ap + (size_t)(wrow + g + 8) * SSd;

    // ==== PASS 2: stages 0-3 reuse cached K (V producer only); 4-7 convert K+V ====
    for (int st = 0; st < 8; ++st) {
        if (st > 0) __syncthreads();
        int koff;
        if (st < 4) {
            koff = st * KTILE;                 // cached K: no producer
        } else {
            koff = SM_KW;
            conv_tile(Kp + (size_t)(st * 128) * (HH * EE), SM_KW);
        }
        conv_tile(Vp + (size_t)(st * 128) * (HH * DD), SM_V);
        __syncthreads();

        const uint32_t bq = laneQK + koff;
        const bool diag = (st == lt);
        #pragma unroll
        for (int pkt = 0; pkt < 8; ++pkt) {
            float s0[4] = {0.f, 0.f, 0.f, 0.f};
            float s1[4] = {0.f, 0.f, 0.f, 0.f};
            #pragma unroll
            for (int kt = 0; kt < 4; ++kt) {
                uint32_t bb[4];
                ldsm4(bb, bq + pkt * (16 * KSTR) + kt * 32);
                mma16816(s0, qh[kt], bb[0], bb[1]);
                mma16816(s0, ql[kt], bb[0], bb[1]);
                mma16816(s1, qh[kt], bb[2], bb[3]);
                mma16816(s1, ql[kt], bb[2], bb[3]);
            }

            s0[0] = fast_exp2(s0[0]); s0[1] = fast_exp2(s0[1]);
            s0[2] = fast_exp2(s0[2]); s0[3] = fast_exp2(s0[3]);
            s1[0] = fast_exp2(s1[0]); s1[1] = fast_exp2(s1[1]);
            s1[2] = fast_exp2(s1[2]); s1[3] = fast_exp2(s1[3]);
            if (diag) {
                int c0 = pkt * 16 + 2 * m;
                int c1 = c0 + 8;
                if (c0 == lrow_lo)     s0[0] = 0.f;
                if (c0 + 1 == lrow_lo) s0[1] = 0.f;
                if (c0 == lrow_hi)     s0[2] = 0.f;
                if (c0 + 1 == lrow_hi) s0[3] = 0.f;
                if (c1 == lrow_lo)     s1[0] = 0.f;
                if (c1 + 1 == lrow_lo) s1[1] = 0.f;
                if (c1 == lrow_hi)     s1[2] = 0.f;
                if (c1 + 1 == lrow_hi) s1[3] = 0.f;
            }

            s0[0] *= ri_lo; s0[1] *= ri_lo; s0[2] *= ri_hi; s0[3] *= ri_hi;
            s1[0] *= ri_lo; s1[1] *= ri_lo; s1[2] *= ri_hi; s1[3] *= ri_hi;

            // streaming (evict-first) A stores: write-once data, keep L2 for K/V
            int c0g = st * 128 + pkt * 16 + 2 * m;
            __stcs(reinterpret_cast<float2*>(Arow_lo + c0g),     make_float2(s0[0], s0[1]));
            __stcs(reinterpret_cast<float2*>(Arow_hi + c0g),     make_float2(s0[2], s0[3]));
            __stcs(reinterpret_cast<float2*>(Arow_lo + c0g + 8), make_float2(s1[0], s1[1]));
            __stcs(reinterpret_cast<float2*>(Arow_hi + c0g + 8), make_float2(s1[2], s1[3]));

            uint32_t pa[4];
            pa[0] = pack2h(s0[0], s0[1]);
            pa[1] = pack2h(s0[2], s0[3]);
            pa[2] = pack2h(s1[0], s1[1]);
            pa[3] = pack2h(s1[2], s1[3]);

            #pragma unroll
            for (int j = 0; j < 4; ++j) {
                uint32_t vv[4];
                ldsm4t(vv, basePV + pkt * (16 * KSTR) + j * 32);
                mma16816(o[2 * j],     pa, vv[0], vv[1]);
                mma16816(o[2 * j + 1], pa, vv[2], vv[3]);
            }
        }
    }

    // ---- O write (already normalized) ----
    {
        float* o0 = Op + (size_t)(wrow + g) * (HH * DD) + 2 * m;
        float* o1 = Op + (size_t)(wrow + g + 8) * (HH * DD) + 2 * m;
        #pragma unroll
        for (int ont = 0; ont < 8; ++ont) {
            *reinterpret_cast<float2*>(o0 + ont * 8) = make_float2(o[ont][0], o[ont][1]);
            *reinterpret_cast<float2*>(o1 + ont * 8) = make_float2(o[ont][2], o[ont][3]);
        }
    }
}

extern "C" void kernel_launch(void* const* d_in, const int* in_sizes, int n_in,
                              void* d_out, int out_size) {
    (void)in_sizes; (void)n_in; (void)out_size;
    const float* q     = (const float*)d_in[0];
    const float* k     = (const float*)d_in[1];
    const float* v     = (const float*)d_in[2];
    const float* scale = (const float*)d_in[3];
    float* out = (float*)d_out;

    static bool attr_set = false;
    if (!attr_set) {
        cudaFuncSetAttribute(attn_mma, cudaFuncAttributeMaxDynamicSharedMemorySize, SMEM_TOTAL);
        attr_set = true;
    }
    dim3 grid(BB * HH * (LL / 128));   // 768
    attn_mma<<<grid, NT, SMEM_TOTAL>>>(q, k, v, scale, out);
}

// round 17
// speedup vs baseline: 1.0006x; 1.0006x over previous
#include <cuda_runtime.h>
#include <cuda_fp16.h>
#include <cstdint>

#define BB 8
#define LL 1024
#define SSd 1024
#define HH 12
#define EE 64
#define DD 64
#define NT 256

#define KSTR 144                    // bytes per f16 row (64 f16 + 16B pad)
#define KTILE (128 * KSTR)          // 18432
#define SM_KW (4 * KTILE)           // working K slot (stages 4-7)
#define SM_V  (5 * KTILE)           // V slot
#define SM_ROW (6 * KTILE)          // rowsums
#define SMEM_TOTAL (SM_ROW + 512)   // 111104 B -> 2 CTAs/SM

// m16n8k16 row.col f32.f16.f16.f32
__device__ __forceinline__ void mma16816(float* c, const uint32_t* a, uint32_t b0, uint32_t b1) {
    asm volatile(
        "mma.sync.aligned.m16n8k16.row.col.f32.f16.f16.f32 "
        "{%0,%1,%2,%3}, {%4,%5,%6,%7}, {%8,%9}, {%0,%1,%2,%3};"
        : "+f"(c[0]), "+f"(c[1]), "+f"(c[2]), "+f"(c[3])
        : "r"(a[0]), "r"(a[1]), "r"(a[2]), "r"(a[3]), "r"(b0), "r"(b1));
}

__device__ __forceinline__ void ldsm4(uint32_t* r, uint32_t saddr) {
    asm volatile("ldmatrix.sync.aligned.m8n8.x4.shared.b16 {%0,%1,%2,%3}, [%4];"
        : "=r"(r[0]), "=r"(r[1]), "=r"(r[2]), "=r"(r[3]) : "r"(saddr));
}
__device__ __forceinline__ void ldsm4t(uint32_t* r, uint32_t saddr) {
    asm volatile("ldmatrix.sync.aligned.m8n8.x4.trans.shared.b16 {%0,%1,%2,%3}, [%4];"
        : "=r"(r[0]), "=r"(r[1]), "=r"(r[2]), "=r"(r[3]) : "r"(saddr));
}

// fast exp2(y), log2-domain input; deg-4 Taylor, no clamp (|y| bounded by data)
__device__ __forceinline__ float fast_exp2(float y) {
    float nf = y + 12582912.0f;
    float f  = y - (nf - 12582912.0f);
    int   ni = __float_as_int(nf) - 0x4B400000;
    float p = 0.009618129107628477f;
    p = fmaf(p, f, 0.05550410866482158f);
    p = fmaf(p, f, 0.2402265069591007f);
    p = fmaf(p, f, 0.6931471805599453f);
    p = fmaf(p, f, 1.0f);
    return __int_as_float((ni + 127) << 23) * p;
}

// 2-term f16 split
__device__ __forceinline__ void split2h(float a, float b, uint32_t& hi, uint32_t& lo) {
    __half ha = __float2half_rn(a), hb = __float2half_rn(b);
    __half2 hh = __halves2half2(ha, hb);
    hi = *reinterpret_cast<uint32_t*>(&hh);
    __half2 ll = __floats2half2_rn(a - __half2float(ha), b - __half2float(hb));
    lo = *reinterpret_cast<uint32_t*>(&ll);
}
__device__ __forceinline__ uint32_t pack2h(float a, float b) {
    __half2 hh = __floats2half2_rn(a, b);
    return *reinterpret_cast<uint32_t*>(&hh);
}

__global__ void __launch_bounds__(NT, 2)
attn_mma(const float* __restrict__ q, const float* __restrict__ k,
         const float* __restrict__ v, const float* __restrict__ scale,
         float* __restrict__ out)
{
    extern __shared__ char smc[];
    float* sRow = reinterpret_cast<float*>(smc + SM_ROW);
    const uint32_t smem_u = (uint32_t)__cvta_generic_to_shared(smc);

    const int tid  = threadIdx.x;
    const int wid  = tid >> 5;
    const int lane = tid & 31;
    const int g    = lane >> 2;
    const int m    = lane & 3;

    const int lt = blockIdx.x & 7;
    const int h  = (blockIdx.x >> 3) % HH;
    const int b  = blockIdx.x / (8 * HH);
    const int row0 = lt * 128;
    const int wrow = wid * 16;

    const float sc = __ldg(scale + h) * 1.4426950408889634f;   // fold log2(e)

    const float* Qp = q + (((size_t)b * LL + row0) * HH + h) * EE;
    const float* Kp = k + ((size_t)b * SSd * HH + h) * EE;
    const float* Vp = v + ((size_t)b * SSd * HH + h) * DD;
    float* Op = out + (((size_t)b * LL + row0) * HH + h) * DD;
    float* Ap = out + (size_t)BB * LL * HH * DD
                    + (((size_t)b * HH + h) * LL + row0) * (size_t)SSd;

    // fp32 -> f16 tile converter: COALESCED round-12 mapping
    // (16 lanes per 256B row, one LDG.128 + one STS.64 per iteration)
    auto conv_tile = [&](const float* src, int dstoff) {
        #pragma unroll
        for (int i = 0; i < 8; ++i) {
            int idx = tid + i * NT;          // 0..2047
            int s = idx >> 4, e4 = idx & 15;
            float4 t = *reinterpret_cast<const float4*>(
                src + (size_t)s * (HH * EE) + e4 * 4);
            *reinterpret_cast<uint2*>(smc + dstoff + s * KSTR + e4 * 8) =
                make_uint2(pack2h(t.x, t.y), pack2h(t.z, t.w));
        }
    };

    // lane-parts of ldsm bases (tile offset added per stage)
    const uint32_t laneQK = smem_u + (lane & 7) * KSTR + ((lane >> 3) & 1) * 16
                          + (lane >> 4) * (8 * KSTR);
    const uint32_t basePV = smem_u + SM_V
                          + ((lane & 7) + ((lane >> 3) & 1) * 8) * KSTR
                          + (lane >> 4) * 16;

    // ---- Q fragments (persistent): 4 k-tiles, f16 hi+lo ----
    uint32_t qh[4][4], ql[4][4];
    {
        const float* q0 = Qp + (size_t)(wrow + g) * (HH * EE);
        const float* q1 = Qp + (size_t)(wrow + g + 8) * (HH * EE);
        #pragma unroll
        for (int kt = 0; kt < 4; ++kt) {
            int e0 = kt * 16 + 2 * m;
            float2 a0 = *reinterpret_cast<const float2*>(q0 + e0);
            float2 a1 = *reinterpret_cast<const float2*>(q1 + e0);
            float2 a2 = *reinterpret_cast<const float2*>(q0 + e0 + 8);
            float2 a3 = *reinterpret_cast<const float2*>(q1 + e0 + 8);
            split2h(a0.x * sc, a0.y * sc, qh[kt][0], ql[kt][0]);
            split2h(a1.x * sc, a1.y * sc, qh[kt][1], ql[kt][1]);
            split2h(a2.x * sc, a2.y * sc, qh[kt][2], ql[kt][2]);
            split2h(a3.x * sc, a3.y * sc, qh[kt][3], ql[kt][3]);
        }
    }

    const int lrow_lo = wrow + g;     // diag col within stage st==lt
    const int lrow_hi = lrow_lo + 8;
    float rsum_lo = 0.f, rsum_hi = 0.f;

    // ======== PASS 1: rowsums (Q-hi only); stages 0-3 convert K into cache slots ========
    for (int st = 0; st < 8; ++st) {
        if (st >= 5) __syncthreads();          // only Kwork overwrites need a pre-sync
        const int koff = (st < 4) ? st * KTILE : SM_KW;
        conv_tile(Kp + (size_t)(st * 128) * (HH * EE), koff);
        __syncthreads();

        const uint32_t bq = laneQK + koff;
        const bool diag = (st == lt);
        #pragma unroll
        for (int pkt = 0; pkt < 8; ++pkt) {
            float s0[4] = {0.f, 0.f, 0.f, 0.f};
            float s1[4] = {0.f, 0.f, 0.f, 0.f};
            #pragma unroll
            for (int kt = 0; kt < 4; ++kt) {
                uint32_t bb[4];
                ldsm4(bb, bq + pkt * (16 * KSTR) + kt * 32);
                mma16816(s0, qh[kt], bb[0], bb[1]);
                mma16816(s1, qh[kt], bb[2], bb[3]);
            }
            s0[0] = fast_exp2(s0[0]); s0[1] = fast_exp2(s0[1]);
            s0[2] = fast_exp2(s0[2]); s0[3] = fast_exp2(s0[3]);
            s1[0] = fast_exp2(s1[0]); s1[1] = fast_exp2(s1[1]);
            s1[2] = fast_exp2(s1[2]); s1[3] = fast_exp2(s1[3]);
            if (diag) {
                int c0 = pkt * 16 + 2 * m;
                int c1 = c0 + 8;
                if (c0 == lrow_lo)     s0[0] = 0.f;
                if (c0 + 1 == lrow_lo) s0[1] = 0.f;
                if (c0 == lrow_hi)     s0[2] = 0.f;
                if (c0 + 1 == lrow_hi) s0[3] = 0.f;
                if (c1 == lrow_lo)     s1[0] = 0.f;
                if (c1 + 1 == lrow_lo) s1[1] = 0.f;
                if (c1 == lrow_hi)     s1[2] = 0.f;
                if (c1 + 1 == lrow_hi) s1[3] = 0.f;
            }
            rsum_lo += (s0[0] + s0[1]) + (s1[0] + s1[1]);
            rsum_hi += (s0[2] + s0[3]) + (s1[2] + s1[3]);
        }
    }

    rsum_lo += __shfl_xor_sync(0xffffffffu, rsum_lo, 1);
    rsum_lo += __shfl_xor_sync(0xffffffffu, rsum_lo, 2);
    rsum_hi += __shfl_xor_sync(0xffffffffu, rsum_hi, 1);
    rsum_hi += __shfl_xor_sync(0xffffffffu, rsum_hi, 2);
    if (m == 0) {
        sRow[wrow + g] = rsum_lo;
        sRow[wrow + g + 8] = rsum_hi;
    }
    __syncthreads();
    const float ri_lo = 1.0f / sRow[wrow + g];
    const float ri_hi = 1.0f / sRow[wrow + g + 8];

    float o[8][4];
    #pragma unroll
    for (int i = 0; i < 8; ++i)
        #pragma unroll
        for (int j = 0; j < 4; ++j) o[i][j] = 0.f;

    float* Arow_lo = Ap + (size_t)(wrow + g) * SSd;
    float* Arow_hi = Ap + (size_t)(wrow + g + 8) * SSd;

    // ==== PASS 2: stages 0-3 reuse cached K (V producer only); 4-7 convert K+V ====
    for (int st = 0; st < 8; ++st) {
        if (st > 0) __syncthreads();
        int koff;
        if (st < 4) {
            koff = st * KTILE;                 // cached K: no producer
        } else {
            koff = SM_KW;
            conv_tile(Kp + (size_t)(st * 128) * (HH * EE), SM_KW);
        }
        conv_tile(Vp + (size_t)(st * 128) * (HH * DD), SM_V);
        __syncthreads();

        const uint32_t bq = laneQK + koff;
        const bool diag = (st == lt);
        #pragma unroll
        for (int pkt = 0; pkt < 8; ++pkt) {
            float s0[4] = {0.f, 0.f, 0.f, 0.f};
            float s1[4] = {0.f, 0.f, 0.f, 0.f};
            #pragma unroll
            for (int kt = 0; kt < 4; ++kt) {
                uint32_t bb[4];
                ldsm4(bb, bq + pkt * (16 * KSTR) + kt * 32);
                mma16816(s0, qh[kt], bb[0], bb[1]);
                mma16816(s0, ql[kt], bb[0], bb[1]);
                mma16816(s1, qh[kt], bb[2], bb[3]);
                mma16816(s1, ql[kt], bb[2], bb[3]);
            }

            s0[0] = fast_exp2(s0[0]); s0[1] = fast_exp2(s0[1]);
            s0[2] = fast_exp2(s0[2]); s0[3] = fast_exp2(s0[3]);
            s1[0] = fast_exp2(s1[0]); s1[1] = fast_exp2(s1[1]);
            s1[2] = fast_exp2(s1[2]); s1[3] = fast_exp2(s1[3]);
            if (diag) {
                int c0 = pkt * 16 + 2 * m;
                int c1 = c0 + 8;
                if (c0 == lrow_lo)     s0[0] = 0.f;
                if (c0 + 1 == lrow_lo) s0[1] = 0.f;
                if (c0 == lrow_hi)     s0[2] = 0.f;
                if (c0 + 1 == lrow_hi) s0[3] = 0.f;
                if (c1 == lrow_lo)     s1[0] = 0.f;
                if (c1 + 1 == lrow_lo) s1[1] = 0.f;
                if (c1 == lrow_hi)     s1[2] = 0.f;
                if (c1 + 1 == lrow_hi) s1[3] = 0.f;
            }

            s0[0] *= ri_lo; s0[1] *= ri_lo; s0[2] *= ri_hi; s0[3] *= ri_hi;
            s1[0] *= ri_lo; s1[1] *= ri_lo; s1[2] *= ri_hi; s1[3] *= ri_hi;

            // streaming (evict-first) A stores: write-once data, keep L2 for K/V
            int c0g = st * 128 + pkt * 16 + 2 * m;
            __stcs(reinterpret_cast<float2*>(Arow_lo + c0g),     make_float2(s0[0], s0[1]));
            __stcs(reinterpret_cast<float2*>(Arow_hi + c0g),     make_float2(s0[2], s0[3]));
            __stcs(reinterpret_cast<float2*>(Arow_lo + c0g + 8), make_float2(s1[0], s1[1]));
            __stcs(reinterpret_cast<float2*>(Arow_hi + c0g + 8), make_float2(s1[2], s1[3]));

            uint32_t pa[4];
            pa[0] = pack2h(s0[0], s0[1]);
            pa[1] = pack2h(s0[2], s0[3]);
            pa[2] = pack2h(s1[0], s1[1]);
            pa[3] = pack2h(s1[2], s1[3]);

            #pragma unroll
            for (int j = 0; j < 4; ++j) {
                uint32_t vv[4];
                ldsm4t(vv, basePV + pkt * (16 * KSTR) + j * 32);
                mma16816(o[2 * j],     pa, vv[0], vv[1]);
                mma16816(o[2 * j + 1], pa, vv[2], vv[3]);
            }
        }
    }

    // ---- O write (already normalized) ----
    {
        float* o0 = Op + (size_t)(wrow + g) * (HH * DD) + 2 * m;
        float* o1 = Op + (size_t)(wrow + g + 8) * (HH * DD) + 2 * m;
        #pragma unroll
        for (int ont = 0; ont < 8; ++ont) {
            *reinterpret_cast<float2*>(o0 + ont * 8) = make_float2(o[ont][0], o[ont][1]);
            *reinterpret_cast<float2*>(o1 + ont * 8) = make_float2(o[ont][2], o[ont][3]);
        }
    }
}

extern "C" void kernel_launch(void* const* d_in, const int* in_sizes, int n_in,
                              void* d_out, int out_size) {
    (void)in_sizes; (void)n_in; (void)out_size;
    const float* q     = (const float*)d_in[0];
    const float* k     = (const float*)d_in[1];
    const float* v     = (const float*)d_in[2];
    const float* scale = (const float*)d_in[3];
    float* out = (float*)d_out;

    static bool attr_set = false;
    if (!attr_set) {
        cudaFuncSetAttribute(attn_mma, cudaFuncAttributeMaxDynamicSharedMemorySize, SMEM_TOTAL);
        attr_set = true;
    }
    dim3 grid(BB * HH * (LL / 128));   // 768
    attn_mma<<<grid, NT, SMEM_TOTAL>>>(q, k, v, scale, out);
}